// round 5
// baseline (speedup 1.0000x reference)
#include <cuda_runtime.h>

// KVQuantizerDequantizer: asymmetric 4-bit RTN quantize+dequantize, groups of
// 128 floats along last dim.
// Persistent grid-stride version: grid = 152 SMs x 8 blocks, each warp handles
// 4 groups per iteration (8 lanes/group, 4 float4 loads per thread, MLP=4).
// Single wave -> no inter-wave launch/drain bubbles; loads of iteration i+1
// issue right after the (non-blocking) stores of iteration i.

#define MAXQ 15.0f
#define EPS 1e-8f

__global__ void __launch_bounds__(256, 8)
kvq_kernel(const float* __restrict__ x, float* __restrict__ out, unsigned n_groups) {
    const unsigned lane = threadIdx.x & 31u;
    const unsigned sl   = lane & 7u;            // lane within 8-lane octet
    const unsigned wid  = threadIdx.x >> 5;     // warp in block

    const unsigned warps_per_block = blockDim.x >> 5;
    unsigned group = (blockIdx.x * warps_per_block + wid) * 4u + (lane >> 3);
    const unsigned stride = gridDim.x * warps_per_block * 4u;

    for (; group < n_groups; group += stride) {
        const float4* gp = reinterpret_cast<const float4*>(x) + (size_t)group * 32u;

        // 4 independent loads, front-batched (MLP=4)
        float4 a = gp[sl];
        float4 b = gp[sl + 8];
        float4 c = gp[sl + 16];
        float4 d = gp[sl + 24];

        // local min/max over 16 values
        float mn = fminf(fminf(fminf(a.x, a.y), fminf(a.z, a.w)),
                         fminf(fminf(b.x, b.y), fminf(b.z, b.w)));
        mn = fminf(mn, fminf(fminf(fminf(c.x, c.y), fminf(c.z, c.w)),
                             fminf(fminf(d.x, d.y), fminf(d.z, d.w))));
        float mx = fmaxf(fmaxf(fmaxf(a.x, a.y), fmaxf(a.z, a.w)),
                         fmaxf(fmaxf(b.x, b.y), fmaxf(b.z, b.w)));
        mx = fmaxf(mx, fmaxf(fmaxf(fmaxf(c.x, c.y), fmaxf(c.z, c.w)),
                             fmaxf(fmaxf(d.x, d.y), fmaxf(d.z, d.w))));

        // butterfly within the 8-lane octet (xor 1,2,4 stays inside)
        #pragma unroll
        for (int off = 1; off < 8; off <<= 1) {
            mn = fminf(mn, __shfl_xor_sync(0xffffffffu, mn, off));
            mx = fmaxf(mx, __shfl_xor_sync(0xffffffffu, mx, off));
        }

        // scale / offset (CLIP_RATIO = 1.0); one true division per thread
        const float scale  = fmaxf((mx - mn) / MAXQ, EPS);
        const float rscale = 1.0f / scale;
        const float offset = rintf(-mn * rscale);

        // quantize + dequantize
        #define QDQ(e) do { \
            float q = fminf(fmaxf(rintf((e) * rscale) + offset, 0.0f), MAXQ); \
            (e) = (q - offset) * scale; \
        } while (0)
        QDQ(a.x); QDQ(a.y); QDQ(a.z); QDQ(a.w);
        QDQ(b.x); QDQ(b.y); QDQ(b.z); QDQ(b.w);
        QDQ(c.x); QDQ(c.y); QDQ(c.z); QDQ(c.w);
        QDQ(d.x); QDQ(d.y); QDQ(d.z); QDQ(d.w);
        #undef QDQ

        float4* og = reinterpret_cast<float4*>(out) + (size_t)group * 32u;
        og[sl]      = a;
        og[sl + 8]  = b;
        og[sl + 16] = c;
        og[sl + 24] = d;
    }
}

extern "C" void kernel_launch(void* const* d_in, const int* in_sizes, int n_in,
                              void* d_out, int out_size) {
    const float* x = (const float*)d_in[0];
    float* out = (float*)d_out;

    unsigned n_groups = (unsigned)((long long)in_sizes[0] / 128);  // 524288

    const int threads = 256;                 // 8 warps -> 32 groups per iter/block
    const unsigned blocks = 152u * 8u;       // GB300: 152 SMs x occupancy 8

    kvq_kernel<<<blocks, threads>>>(x, out, n_groups);
}

// round 6
// speedup vs baseline: 1.0545x; 1.0545x over previous
#include <cuda_runtime.h>

// KVQuantizerDequantizer: asymmetric 4-bit RTN quantize+dequantize, groups of
// 128 floats along last dim.
// Software-pipelined persistent kernel: 8 lanes/group, 4 groups/warp/iter.
// Double-buffered registers: loads for iteration i+1 are issued BEFORE the
// compute+store of iteration i, so per-warp DRAM latency is exposed only once
// (prologue) and reads overlap writes at the LSU/L2 level.

#define MAXQ 15.0f
#define EPS 1e-8f

__device__ __forceinline__ void qdq_group(float4& a, float4& b, float4& c, float4& d) {
    // local min/max over 16 values
    float mn = fminf(fminf(fminf(a.x, a.y), fminf(a.z, a.w)),
                     fminf(fminf(b.x, b.y), fminf(b.z, b.w)));
    mn = fminf(mn, fminf(fminf(fminf(c.x, c.y), fminf(c.z, c.w)),
                         fminf(fminf(d.x, d.y), fminf(d.z, d.w))));
    float mx = fmaxf(fmaxf(fmaxf(a.x, a.y), fmaxf(a.z, a.w)),
                     fmaxf(fmaxf(b.x, b.y), fmaxf(b.z, b.w)));
    mx = fmaxf(mx, fmaxf(fmaxf(fmaxf(c.x, c.y), fmaxf(c.z, c.w)),
                         fmaxf(fmaxf(d.x, d.y), fmaxf(d.z, d.w))));

    // butterfly within the 8-lane octet (xor 1,2,4 stays inside)
    #pragma unroll
    for (int off = 1; off < 8; off <<= 1) {
        mn = fminf(mn, __shfl_xor_sync(0xffffffffu, mn, off));
        mx = fmaxf(mx, __shfl_xor_sync(0xffffffffu, mx, off));
    }

    const float scale  = fmaxf((mx - mn) / MAXQ, EPS);
    const float rscale = 1.0f / scale;
    const float offset = rintf(-mn * rscale);

    #define QDQ(e) do { \
        float q = fminf(fmaxf(rintf((e) * rscale) + offset, 0.0f), MAXQ); \
        (e) = (q - offset) * scale; \
    } while (0)
    QDQ(a.x); QDQ(a.y); QDQ(a.z); QDQ(a.w);
    QDQ(b.x); QDQ(b.y); QDQ(b.z); QDQ(b.w);
    QDQ(c.x); QDQ(c.y); QDQ(c.z); QDQ(c.w);
    QDQ(d.x); QDQ(d.y); QDQ(d.z); QDQ(d.w);
    #undef QDQ
}

__global__ void __launch_bounds__(256)
kvq_kernel(const float* __restrict__ x, float* __restrict__ out, unsigned n_groups) {
    const unsigned lane = threadIdx.x & 31u;
    const unsigned sl   = lane & 7u;            // lane within 8-lane octet
    const unsigned wid  = threadIdx.x >> 5;

    const unsigned warps_per_block = blockDim.x >> 5;
    unsigned g = (blockIdx.x * warps_per_block + wid) * 4u + (lane >> 3);
    const unsigned stride = gridDim.x * warps_per_block * 4u;
    if (g >= n_groups) return;

    // prologue: load current tile
    const float4* gp = reinterpret_cast<const float4*>(x) + (size_t)g * 32u;
    float4 a = gp[sl], b = gp[sl + 8], c = gp[sl + 16], d = gp[sl + 24];

    for (;;) {
        const unsigned gn = g + stride;
        const bool has_next = gn < n_groups;

        // front-issue next tile's loads (independent registers) BEFORE compute
        float4 a2, b2, c2, d2;
        if (has_next) {
            const float4* gpn = reinterpret_cast<const float4*>(x) + (size_t)gn * 32u;
            a2 = gpn[sl]; b2 = gpn[sl + 8]; c2 = gpn[sl + 16]; d2 = gpn[sl + 24];
        }

        // compute + store current tile (overlaps with next tile's loads)
        qdq_group(a, b, c, d);
        float4* og = reinterpret_cast<float4*>(out) + (size_t)g * 32u;
        og[sl] = a; og[sl + 8] = b; og[sl + 16] = c; og[sl + 24] = d;

        if (!has_next) break;
        g = gn;
        a = a2; b = b2; c = c2; d = d2;
    }
}

extern "C" void kernel_launch(void* const* d_in, const int* in_sizes, int n_in,
                              void* d_out, int out_size) {
    const float* x = (const float*)d_in[0];
    float* out = (float*)d_out;

    unsigned n_groups = (unsigned)((long long)in_sizes[0] / 128);  // 524288

    const int threads = 256;                 // 8 warps -> 32 groups per iter/block
    // ~48 regs -> 5 blocks/SM resident; 152 SMs * 5 = single persistent wave
    const unsigned blocks = 152u * 5u;

    kvq_kernel<<<blocks, threads>>>(x, out, n_groups);
}

// round 7
// speedup vs baseline: 1.1273x; 1.0691x over previous
#include <cuda_runtime.h>

// KVQuantizerDequantizer: asymmetric 4-bit RTN quantize+dequantize, groups of
// 128 floats along last dim. Final config (best measured across 6 rounds):
//  - non-persistent launch: CTA scheduler provides load/store overlap
//  - 8 lanes per group, 4 groups per warp, 4 front-batched float4 loads (MLP=4)
//  - __ldcg loads (L2-only; L1 hit rate is structurally 0 for this stream)
//  - plain stores (streaming hints measured slightly negative)
//  - 32 regs, occupancy 8 blocks/SM

#define MAXQ 15.0f
#define EPS 1e-8f

__global__ void __launch_bounds__(256, 8)
kvq_kernel(const float* __restrict__ x, float* __restrict__ out, unsigned n_groups) {
    const unsigned lane = threadIdx.x & 31u;
    const unsigned sl   = lane & 7u;            // lane within 8-lane octet
    const unsigned warp_global = blockIdx.x * (blockDim.x >> 5) + (threadIdx.x >> 5);
    const unsigned group = warp_global * 4u + (lane >> 3);
    if (group >= n_groups) return;

    const float4* gp = reinterpret_cast<const float4*>(x) + (size_t)group * 32u;

    // 4 independent loads, front-batched (MLP=4), L2-only
    float4 a = __ldcg(&gp[sl]);
    float4 b = __ldcg(&gp[sl + 8]);
    float4 c = __ldcg(&gp[sl + 16]);
    float4 d = __ldcg(&gp[sl + 24]);

    // local min/max over 16 values
    float mn = fminf(fminf(fminf(a.x, a.y), fminf(a.z, a.w)),
                     fminf(fminf(b.x, b.y), fminf(b.z, b.w)));
    mn = fminf(mn, fminf(fminf(fminf(c.x, c.y), fminf(c.z, c.w)),
                         fminf(fminf(d.x, d.y), fminf(d.z, d.w))));
    float mx = fmaxf(fmaxf(fmaxf(a.x, a.y), fmaxf(a.z, a.w)),
                     fmaxf(fmaxf(b.x, b.y), fmaxf(b.z, b.w)));
    mx = fmaxf(mx, fmaxf(fmaxf(fmaxf(c.x, c.y), fmaxf(c.z, c.w)),
                         fmaxf(fmaxf(d.x, d.y), fmaxf(d.z, d.w))));

    // butterfly within the 8-lane octet (xor 1,2,4 stays inside)
    #pragma unroll
    for (int off = 1; off < 8; off <<= 1) {
        mn = fminf(mn, __shfl_xor_sync(0xffffffffu, mn, off));
        mx = fmaxf(mx, __shfl_xor_sync(0xffffffffu, mx, off));
    }

    // scale / offset (CLIP_RATIO = 1.0); one true division per thread
    const float scale  = fmaxf((mx - mn) / MAXQ, EPS);
    const float rscale = 1.0f / scale;
    const float offset = rintf(-mn * rscale);

    // quantize + dequantize
    #define QDQ(e) do { \
        float q = fminf(fmaxf(rintf((e) * rscale) + offset, 0.0f), MAXQ); \
        (e) = (q - offset) * scale; \
    } while (0)
    QDQ(a.x); QDQ(a.y); QDQ(a.z); QDQ(a.w);
    QDQ(b.x); QDQ(b.y); QDQ(b.z); QDQ(b.w);
    QDQ(c.x); QDQ(c.y); QDQ(c.z); QDQ(c.w);
    QDQ(d.x); QDQ(d.y); QDQ(d.z); QDQ(d.w);
    #undef QDQ

    float4* og = reinterpret_cast<float4*>(out) + (size_t)group * 32u;
    og[sl]      = a;
    og[sl + 8]  = b;
    og[sl + 16] = c;
    og[sl + 24] = d;
}

extern "C" void kernel_launch(void* const* d_in, const int* in_sizes, int n_in,
                              void* d_out, int out_size) {
    const float* x = (const float*)d_in[0];
    float* out = (float*)d_out;

    unsigned n_groups = (unsigned)((long long)in_sizes[0] / 128);  // 524288

    const int threads = 256;                   // 8 warps -> 32 groups per block
    unsigned groups_per_block = (threads / 32) * 4;
    unsigned blocks = (n_groups + groups_per_block - 1) / groups_per_block;

    kvq_kernel<<<blocks, threads>>>(x, out, n_groups);
}

// round 8
// speedup vs baseline: 1.1317x; 1.0039x over previous
#include <cuda_runtime.h>

// KVQuantizerDequantizer: asymmetric 4-bit RTN quantize+dequantize, groups of
// 128 floats along last dim.
// Converged config at the measured mixed r/w DRAM ceiling (~6.45 TB/s):
//  - non-persistent launch (CTA scheduler provides load/store overlap)
//  - 8 lanes per group, 4 groups per warp, 4 front-batched float4 loads (MLP=4)
//  - __ldcg loads (L2-only), plain stores
//  - 128-thread CTAs at occupancy 16: finer CTA granularity for smoother
//    overlap and halved final-wave raggedness vs 256-thread CTAs

#define MAXQ 15.0f
#define EPS 1e-8f

__global__ void __launch_bounds__(128, 16)
kvq_kernel(const float* __restrict__ x, float* __restrict__ out, unsigned n_groups) {
    const unsigned lane = threadIdx.x & 31u;
    const unsigned sl   = lane & 7u;            // lane within 8-lane octet
    const unsigned warp_global = blockIdx.x * (blockDim.x >> 5) + (threadIdx.x >> 5);
    const unsigned group = warp_global * 4u + (lane >> 3);
    if (group >= n_groups) return;

    const float4* gp = reinterpret_cast<const float4*>(x) + (size_t)group * 32u;

    // 4 independent loads, front-batched (MLP=4), L2-only
    float4 a = __ldcg(&gp[sl]);
    float4 b = __ldcg(&gp[sl + 8]);
    float4 c = __ldcg(&gp[sl + 16]);
    float4 d = __ldcg(&gp[sl + 24]);

    // local min/max over 16 values
    float mn = fminf(fminf(fminf(a.x, a.y), fminf(a.z, a.w)),
                     fminf(fminf(b.x, b.y), fminf(b.z, b.w)));
    mn = fminf(mn, fminf(fminf(fminf(c.x, c.y), fminf(c.z, c.w)),
                         fminf(fminf(d.x, d.y), fminf(d.z, d.w))));
    float mx = fmaxf(fmaxf(fmaxf(a.x, a.y), fmaxf(a.z, a.w)),
                     fmaxf(fmaxf(b.x, b.y), fmaxf(b.z, b.w)));
    mx = fmaxf(mx, fmaxf(fmaxf(fmaxf(c.x, c.y), fmaxf(c.z, c.w)),
                         fmaxf(fmaxf(d.x, d.y), fmaxf(d.z, d.w))));

    // butterfly within the 8-lane octet (xor 1,2,4 stays inside)
    #pragma unroll
    for (int off = 1; off < 8; off <<= 1) {
        mn = fminf(mn, __shfl_xor_sync(0xffffffffu, mn, off));
        mx = fmaxf(mx, __shfl_xor_sync(0xffffffffu, mx, off));
    }

    // scale / offset (CLIP_RATIO = 1.0); one true division per thread
    const float scale  = fmaxf((mx - mn) / MAXQ, EPS);
    const float rscale = 1.0f / scale;
    const float offset = rintf(-mn * rscale);

    // quantize + dequantize
    #define QDQ(e) do { \
        float q = fminf(fmaxf(rintf((e) * rscale) + offset, 0.0f), MAXQ); \
        (e) = (q - offset) * scale; \
    } while (0)
    QDQ(a.x); QDQ(a.y); QDQ(a.z); QDQ(a.w);
    QDQ(b.x); QDQ(b.y); QDQ(b.z); QDQ(b.w);
    QDQ(c.x); QDQ(c.y); QDQ(c.z); QDQ(c.w);
    QDQ(d.x); QDQ(d.y); QDQ(d.z); QDQ(d.w);
    #undef QDQ

    float4* og = reinterpret_cast<float4*>(out) + (size_t)group * 32u;
    og[sl]      = a;
    og[sl + 8]  = b;
    og[sl + 16] = c;
    og[sl + 24] = d;
}

extern "C" void kernel_launch(void* const* d_in, const int* in_sizes, int n_in,
                              void* d_out, int out_size) {
    const float* x = (const float*)d_in[0];
    float* out = (float*)d_out;

    unsigned n_groups = (unsigned)((long long)in_sizes[0] / 128);  // 524288

    const int threads = 128;                   // 4 warps -> 16 groups per block
    unsigned groups_per_block = (threads / 32) * 4;
    unsigned blocks = (n_groups + groups_per_block - 1) / groups_per_block;

    kvq_kernel<<<blocks, threads>>>(x, out, n_groups);
}

// round 9
// speedup vs baseline: 1.1335x; 1.0016x over previous
#include <cuda_runtime.h>

// KVQuantizerDequantizer: asymmetric 4-bit RTN quantize+dequantize, groups of
// 128 floats along last dim. CONVERGED kernel (best measured over 8 rounds):
//   bench 81.98us / ncu 74.43us @ 6.45 TB/s — the mixed 1:1 r/w DRAM ceiling.
// Config: non-persistent launch (CTA scheduler provides load/store overlap),
// 8 lanes per group, 4 groups per warp, 4 front-batched float4 loads (MLP=4),
// default-cached loads + plain stores (all cache-hint variants measured
// neutral-or-worse), 32 regs, occupancy 8 x 256 threads.

#define MAXQ 15.0f
#define EPS 1e-8f

__global__ void __launch_bounds__(256, 8)
kvq_kernel(const float* __restrict__ x, float* __restrict__ out, unsigned n_groups) {
    const unsigned lane = threadIdx.x & 31u;
    const unsigned sl   = lane & 7u;            // lane within 8-lane octet
    const unsigned warp_global = blockIdx.x * (blockDim.x >> 5) + (threadIdx.x >> 5);
    const unsigned group = warp_global * 4u + (lane >> 3);
    if (group >= n_groups) return;

    const float4* gp = reinterpret_cast<const float4*>(x) + (size_t)group * 32u;

    // 4 independent loads, front-batched (MLP=4)
    float4 a = gp[sl];
    float4 b = gp[sl + 8];
    float4 c = gp[sl + 16];
    float4 d = gp[sl + 24];

    // local min/max over 16 values
    float mn = fminf(fminf(fminf(a.x, a.y), fminf(a.z, a.w)),
                     fminf(fminf(b.x, b.y), fminf(b.z, b.w)));
    mn = fminf(mn, fminf(fminf(fminf(c.x, c.y), fminf(c.z, c.w)),
                         fminf(fminf(d.x, d.y), fminf(d.z, d.w))));
    float mx = fmaxf(fmaxf(fmaxf(a.x, a.y), fmaxf(a.z, a.w)),
                     fmaxf(fmaxf(b.x, b.y), fmaxf(b.z, b.w)));
    mx = fmaxf(mx, fmaxf(fmaxf(fmaxf(c.x, c.y), fmaxf(c.z, c.w)),
                         fmaxf(fmaxf(d.x, d.y), fmaxf(d.z, d.w))));

    // butterfly within the 8-lane octet (xor 1,2,4 stays inside)
    #pragma unroll
    for (int off = 1; off < 8; off <<= 1) {
        mn = fminf(mn, __shfl_xor_sync(0xffffffffu, mn, off));
        mx = fmaxf(mx, __shfl_xor_sync(0xffffffffu, mx, off));
    }

    // scale / offset (CLIP_RATIO = 1.0); one true division per thread
    const float scale  = fmaxf((mx - mn) / MAXQ, EPS);
    const float rscale = 1.0f / scale;
    const float offset = rintf(-mn * rscale);

    // quantize + dequantize (rintf == jnp.round: round-half-to-even under RN)
    #define QDQ(e) do { \
        float q = fminf(fmaxf(rintf((e) * rscale) + offset, 0.0f), MAXQ); \
        (e) = (q - offset) * scale; \
    } while (0)
    QDQ(a.x); QDQ(a.y); QDQ(a.z); QDQ(a.w);
    QDQ(b.x); QDQ(b.y); QDQ(b.z); QDQ(b.w);
    QDQ(c.x); QDQ(c.y); QDQ(c.z); QDQ(c.w);
    QDQ(d.x); QDQ(d.y); QDQ(d.z); QDQ(d.w);
    #undef QDQ

    float4* og = reinterpret_cast<float4*>(out) + (size_t)group * 32u;
    og[sl]      = a;
    og[sl + 8]  = b;
    og[sl + 16] = c;
    og[sl + 24] = d;
}

extern "C" void kernel_launch(void* const* d_in, const int* in_sizes, int n_in,
                              void* d_out, int out_size) {
    const float* x = (const float*)d_in[0];
    float* out = (float*)d_out;

    unsigned n_groups = (unsigned)((long long)in_sizes[0] / 128);  // 524288

    const int threads = 256;                   // 8 warps -> 32 groups per block
    unsigned groups_per_block = (threads / 32) * 4;
    unsigned blocks = (n_groups + groups_per_block - 1) / groups_per_block;

    kvq_kernel<<<blocks, threads>>>(x, out, n_groups);
}